// round 3
// baseline (speedup 1.0000x reference)
#include <cuda_runtime.h>
#include <cstdint>

// LBP semantic dependency, difference-space, symmetric-pair formulation.
// B=2, S=160. 2-CTA cluster per (i,b) problem; pair-parity split keeps the
// transpose partner d[k][j] CTA-local. Each thread updates BOTH directions of
// an unordered pair {j,k} -> no in-place hazard, no intra-phase barriers.

#define S    160
#define S2   25600
#define S3   4096000
#define HS   80
#define PITCH 81
#define RB   (HS*PITCH)          /* 6480 floats: one parity block          */
#define DTY  (2*RB)              /* 12960 floats: one type's d matrix      */
#define NTH  640
#define LOG2E 1.4426950408889634f

/* shared layout (floats) */
#define OFF_D    0                         /* d[3][2][80][81]   38880 */
#define OFF_PS   (3*DTY)                   /* p_s[2][80][81]    12960 */
#define OFF_DB   (OFF_PS + DTY)            /* deltab[160]             */
#define OFF_SE   (OFF_DB + S)
#define OFF_W    (OFF_SE + S)
#define OFF_MJ   (OFF_W + S)
#define OFF_ACCP (OFF_MJ + S)
#define OFF_RS   (OFF_ACCP + S)            /* rowsum partials [4][160] */
#define SMEM_FLOATS (OFF_RS + 4*S)
#define SMEM_BYTES  (SMEM_FLOATS * 4)

extern __shared__ float sm[];

__device__ __forceinline__ uint32_t smem_u32(const void* p) {
    uint32_t a;
    asm("{ .reg .u64 t; cvta.to.shared.u64 t, %1; cvt.u32.u64 %0, t; }"
        : "=r"(a) : "l"(p));
    return a;
}
__device__ __forceinline__ void cluster_sync_() {
    asm volatile("barrier.cluster.arrive.aligned;" ::: "memory");
    asm volatile("barrier.cluster.wait.aligned;" ::: "memory");
}
__device__ __forceinline__ void st_remote_f32(uint32_t laddr, uint32_t rank, float v) {
    asm volatile(
        "{ .reg .b32 r; mapa.shared::cluster.u32 r, %0, %1; "
        "st.shared::cluster.f32 [r], %2; }"
        :: "r"(laddr), "r"(rank), "f"(v) : "memory");
}
__device__ __forceinline__ float ex2f_(float x) {
    float y; asm("ex2.approx.ftz.f32 %0, %1;" : "=f"(y) : "f"(x)); return y;
}
__device__ __forceinline__ float lg2f_(float x) {
    float y; asm("lg2.approx.ftz.f32 %0, %1;" : "=f"(y) : "f"(x)); return y;
}
/* softplus base-2: log2(1 + 2^x) */
__device__ __forceinline__ float sp2(float x) {
    float e = ex2f_(-fabsf(x));
    return fmaxf(x, 0.f) + lg2f_(1.f + e);
}
/* new message difference for direction whose old partner value is dold,
   belief diff dbk, staged (pre-scaled) score ps */
__device__ __forceinline__ float updD(float dbk, float dold, float ps) {
    const float a = dbk - dold;
    return sp2(a + ps) - sp2(a);
}
/* row r, column-slot t  (column k = 2t + colpar(r)) */
__device__ __forceinline__ int dIdx(int r, int t) {
    return ((r & 1) ? RB : 0) + (r >> 1) * PITCH + t;
}

__device__ __forceinline__ bool mask_at(const void* m, bool byteMask, int idx) {
    if (byteMask) return ((const unsigned char*)m)[idx] != 0;
    return ((const uint32_t*)m)[idx] != 0u;
}

__global__ void __launch_bounds__(NTH, 1) __cluster_dims__(2, 1, 1)
lbp_kernel(const float* __restrict__ s_edge,
           const float* __restrict__ s_sib,
           const float* __restrict__ s_cop,
           const float* __restrict__ s_grd,
           const void* __restrict__ mask,
           float* __restrict__ out)
{
    const int tid  = threadIdx.x;
    const int blk  = blockIdx.x;
    const int c    = blk & 1;        /* parity class == cluster rank */
    const int prob = blk >> 1;
    const int i    = prob % S;
    const int b    = prob / S;

    const bool byteMask = (*(const uint32_t*)mask == 0x01010101u);

    float* __restrict__ D0 = sm + OFF_D;
    float* __restrict__ PS = sm + OFF_PS;
    float* __restrict__ DB = sm + OFF_DB;

    /* ---- init ---- */
    for (int x = tid; x < 3 * DTY; x += NTH) D0[x] = 0.f;
    if (tid < S) {
        const int k = tid;
        const bool mk = mask_at(mask, byteMask, b * S2 + k * S + i);
        sm[OFF_W  + k] = (mk && (k != i)) ? 1.f : 0.f;
        sm[OFF_MJ + k] = mk ? 1.f : 0.f;
        sm[OFF_SE + k] = s_edge[b * S2 + k * S + i] * LOG2E;
        DB[k] = 0.f;
        sm[OFF_ACCP + k] = 0.f;
    }
    __syncthreads();
    cluster_sync_();

    const float* Ps[3] = { s_sib + (size_t)b * S3,
                           s_cop + (size_t)b * S3,
                           s_grd + (size_t)b * S3 };

    const uint32_t accpAddr = smem_u32(sm + OFF_ACCP);
    const uint32_t peer = (uint32_t)(c ^ 1);

    for (int it = 0; it < 3; ++it) {
        for (int t = 0; t < 3; ++t) {
            const float* __restrict__ P = Ps[t] + i * S;
            float* __restrict__ D = D0 + t * DTY;

            /* ---- stage the needed p slice: rows r in [0,160), cols of
               parity (r+c)&1. p_s[dIdx(r, tt)] = p[r, i, 2tt+par] * LOG2E */
            #pragma unroll
            for (int u = 0; u < 20; ++u) {
                const int e  = tid + NTH * u;       /* 12800 = 160*80 */
                const int tt = e % HS;
                const int r  = e / HS;
                const int col = 2 * tt + ((r + c) & 1);
                PS[dIdx(r, tt)] = P[r * S2 + col] * LOG2E;
            }
            __syncthreads();

            /* ---- eval: 6400 cells, both directions per unordered pair ---- */
            #pragma unroll 5
            for (int u = 0; u < 10; ++u) {
                const int m = tid + NTH * u;
                const int a = m % HS;
                const int bb = m / HS;
                int j, k;
                bool diag = false;
                if (c == 1)      { j = 2 * a; k = 2 * bb + 1; }
                else if (a < bb) { j = 2 * a; k = 2 * bb; }
                else if (a > bb) { j = 2 * bb + 1; k = 2 * a + 1; }
                else             { j = 2 * a; k = j; diag = true; }

                if (!diag) {
                    const int ikj = dIdx(k, j >> 1);   /* slot of (row k, col j) */
                    const int ijk = dIdx(j, k >> 1);
                    const float dkj = D[ikj], djk = D[ijk];
                    const float pkj = PS[ikj], pjk = PS[ijk];
                    const float dbk = DB[k],  dbj = DB[j];
                    const float nJK = updD(dbk, dkj, pkj); /* -> d[j][k] */
                    const float nKJ = updD(dbj, djk, pjk); /* -> d[k][j] */
                    D[ijk] = nJK;
                    D[ikj] = nKJ;
                } else {
                    /* two self-pairs: (2a,2a) and (2a+1,2a+1) */
                    const int i0 = dIdx(j, j >> 1);
                    const int i1 = dIdx(j + 1, j >> 1);
                    const float d0 = D[i0], d1 = D[i1];
                    const float n0 = updD(DB[j],     d0, PS[i0]);
                    const float n1 = updD(DB[j + 1], d1, PS[i1]);
                    D[i0] = n0;
                    D[i1] = n1;
                }
            }
            __syncthreads();   /* d[t] final; PS free for next type */
        }

        /* ---- rowsum reduction over all 3 d matrices ---- */
        {
            const int j = tid % S;
            const int q = tid / S;           /* 0..3 */
            const int cp = (j + c) & 1;      /* column parity for row j */
            float acc = 0.f;
            #pragma unroll
            for (int t = 0; t < 3; ++t) {
                const float* __restrict__ D = D0 + t * DTY;
                #pragma unroll
                for (int u = 0; u < 20; ++u) {
                    const int tt = q * 20 + u;
                    const int k  = 2 * tt + cp;
                    const float v = D[dIdx(j, tt)];
                    acc += (k != j) ? sm[OFF_W + k] * v : 0.f;
                }
            }
            sm[OFF_RS + q * S + j] = acc;
        }
        __syncthreads();

        /* ---- belief update + cluster exchange ---- */
        float totLocal = 0.f;
        if (tid < S) {
            totLocal = sm[OFF_RS + tid] + sm[OFF_RS + S + tid]
                     + sm[OFF_RS + 2 * S + tid] + sm[OFF_RS + 3 * S + tid];
            st_remote_f32(accpAddr + 4u * (uint32_t)tid, peer, totLocal);
        }
        cluster_sync_();   /* peer partial landed */
        if (tid < S) {
            const float tot = totLocal + sm[OFF_ACCP + tid];
            DB[tid] = sm[OFF_SE + tid] + sm[OFF_MJ + tid] * tot;
        }
        cluster_sync_();   /* ACCP consumed; DB visible cluster-wide */
    }

    /* ---- output: out[b, j, i, :] = softmax over channels (base-2) ---- */
    if (c == 0 && tid < S) {
        const float Dv = DB[tid];
        const float e  = ex2f_(-fabsf(Dv));
        const float pb = 1.f / (1.f + e);
        const float ps = e * pb;
        const float p1 = (Dv >= 0.f) ? pb : ps;
        const float p0 = (Dv >= 0.f) ? ps : pb;
        float* o = out + ((size_t)((b * S + tid) * S + i)) * 2;
        o[0] = p0;
        o[1] = p1;
    }
}

extern "C" void kernel_launch(void* const* d_in, const int* in_sizes, int n_in,
                              void* d_out, int out_size) {
    (void)in_sizes; (void)n_in; (void)out_size;
    cudaFuncSetAttribute(lbp_kernel,
                         cudaFuncAttributeMaxDynamicSharedMemorySize, SMEM_BYTES);
    const float* s_edge = (const float*)d_in[0];
    const float* s_sib  = (const float*)d_in[1];
    const float* s_cop  = (const float*)d_in[2];
    const float* s_grd  = (const float*)d_in[3];
    const void*  mask   = d_in[4];
    float* outp = (float*)d_out;

    lbp_kernel<<<2 * S * 2, NTH, SMEM_BYTES>>>(
        s_edge, s_sib, s_cop, s_grd, mask, outp);
}

// round 5
// speedup vs baseline: 1.8164x; 1.8164x over previous
#include <cuda_runtime.h>
#include <cstdint>

// LBP semantic dependency, difference-space. 6-CTA cluster per (i,b) problem:
// rank r -> (type t = r>>1, parity c = r&1). Each CTA holds d[t] restricted to
// cells (j,k) with (j+k)&1==c (transpose partner same class -> CTA-local),
// plus the matching p-slice staged in smem ONCE (p is iteration-invariant).
// 107.5 KB smem/CTA -> 2 CTAs/SM for latency hiding.

#define S    160
#define S2   25600
#define S3   4096000
#define HS   80
#define DP   81          /* d pitch (odd: conflict-free row writes) */
#define PP   80          /* ps pitch (transpose reads conflict-free) */
#define NTH  512
#define LOG2E 1.4426950408889634f

/* shared layout (floats) */
#define OFF_D    0                    /* d[160][81] = 12960 */
#define OFF_PS   12960                /* ps[160][80] = 12800 */
#define OFF_DB   25760                /* deltab[160] */
#define OFF_SE   25920
#define OFF_W    26080
#define OFF_MJ   26240
#define OFF_RS   26400                /* local rowsum[160] */
#define OFF_ACC  26560                /* peer partial sums [2][160] */
#define SMEM_FLOATS (OFF_ACC + 2*S)
#define SMEM_BYTES  (SMEM_FLOATS * 4)

extern __shared__ float sm[];

__device__ __forceinline__ uint32_t smem_u32(const void* p) {
    uint32_t a;
    asm("{ .reg .u64 t; cvta.to.shared.u64 t, %1; cvt.u32.u64 %0, t; }"
        : "=r"(a) : "l"(p));
    return a;
}
__device__ __forceinline__ void cluster_sync_() {
    asm volatile("barrier.cluster.arrive.aligned;" ::: "memory");
    asm volatile("barrier.cluster.wait.aligned;" ::: "memory");
}
__device__ __forceinline__ void red_remote_add_f32(uint32_t laddr, uint32_t rank, float v) {
    asm volatile(
        "{ .reg .b32 r; mapa.shared::cluster.u32 r, %0, %1; "
        "red.relaxed.cluster.shared::cluster.add.f32 [r], %2; }"
        :: "r"(laddr), "r"(rank), "f"(v) : "memory");
}
__device__ __forceinline__ float ex2f_(float x) {
    float y; asm("ex2.approx.ftz.f32 %0, %1;" : "=f"(y) : "f"(x)); return y;
}
__device__ __forceinline__ float lg2f_(float x) {
    float y; asm("lg2.approx.ftz.f32 %0, %1;" : "=f"(y) : "f"(x)); return y;
}
/* softplus base-2: log2(1 + 2^x), stable for all x */
__device__ __forceinline__ float sp2(float x) {
    float e = ex2f_(-fabsf(x));
    return fmaxf(x, 0.f) + lg2f_(1.f + e);
}
__device__ __forceinline__ bool mask_at(const void* m, bool byteMask, int idx) {
    if (byteMask) return ((const unsigned char*)m)[idx] != 0;
    return ((const uint32_t*)m)[idx] != 0u;
}

__global__ void __launch_bounds__(NTH, 2) __cluster_dims__(6, 1, 1)
lbp_kernel(const float* __restrict__ s_edge,
           const float* __restrict__ s_sib,
           const float* __restrict__ s_cop,
           const float* __restrict__ s_grd,
           const void* __restrict__ mask,
           float* __restrict__ out)
{
    const int tid  = threadIdx.x;
    const int bx   = blockIdx.x;
    const int rank = bx % 6;
    const int prob = bx / 6;
    const int i    = prob % S;
    const int b    = prob / S;
    const int t    = rank >> 1;      /* score type */
    const int c    = rank & 1;       /* pair-parity class */

    const bool byteMask = (*(const uint32_t*)mask == 0x01010101u);

    float* __restrict__ D  = sm + OFF_D;
    float* __restrict__ PS = sm + OFF_PS;
    float* __restrict__ DB = sm + OFF_DB;

    const float* __restrict__ P =
        (t == 0 ? s_sib : (t == 1 ? s_cop : s_grd)) + (size_t)b * S3 + i * S;

    /* ---- init: zero d, stage p-slice (once!), scalars ---- */
    #pragma unroll 4
    for (int u = 0; u < 26; ++u) {
        const int x = tid + NTH * u;
        if (x < S * DP) D[x] = 0.f;
    }
    #pragma unroll 5
    for (int u = 0; u < 50; ++u) {
        const int e   = tid + NTH * u;          /* 25600 = 512*50 exactly */
        const int col = e % S;
        const int r   = e / S;
        const float val = P[(size_t)r * S2 + col] * LOG2E;
        if (((r + col) & 1) == c) PS[r * PP + (col >> 1)] = val;
    }
    if (tid < S) {
        const int k = tid;
        const bool mk = mask_at(mask, byteMask, b * S2 + k * S + i);
        sm[OFF_W  + k] = (mk && (k != i)) ? 1.f : 0.f;
        sm[OFF_MJ + k] = mk ? 1.f : 0.f;
        sm[OFF_SE + k] = s_edge[b * S2 + k * S + i] * LOG2E;
        DB[k] = 0.f;
        sm[OFF_RS + k] = 0.f;
        sm[OFF_ACC + k] = 0.f;
        sm[OFF_ACC + S + k] = 0.f;
    }
    __syncthreads();
    cluster_sync_();   /* all ranks' ACC zeroed before any remote red */

    const uint32_t accAddr = smem_u32(sm + OFF_ACC);
    float dbFinal = 0.f;

    for (int it = 0; it < 3; ++it) {
        /* ---- stage transpose partners d_old[k][j] into regs ----
           thread cell (jv, k) with k = kB + 32*a; partner slot for
           d[k][jv] is row k, column jv>>1 -> row stride per a is 32*DP */
        float dreg[25];
        #pragma unroll
        for (int v = 0; v < 5; ++v) {
            const int jm  = tid + NTH * v;
            const int kkB = jm / S;
            const int jv  = jm - kkB * S;
            const int kB  = 2 * kkB + (c ^ (jv & 1));
            const int tb  = kB * DP + (jv >> 1);
            #pragma unroll
            for (int a = 0; a < 5; ++a)
                dreg[v * 5 + a] = D[tb + DP * 32 * a];
        }
        __syncthreads();   /* all reads of d before any writes */

        /* ---- compute new message differences ---- */
        float acc[5];
        #pragma unroll
        for (int v = 0; v < 5; ++v) {
            const int jm  = tid + NTH * v;
            const int kkB = jm / S;
            const int jv  = jm - kkB * S;
            const int par = c ^ (jv & 1);
            const int kB  = 2 * kkB + par;
            const int psb = kB * PP + (jv >> 1);
            const int wb  = jv * DP + kkB;
            float av = 0.f;
            #pragma unroll
            for (int a = 0; a < 5; ++a) {
                const int k  = kB + 32 * a;
                const float dold = dreg[v * 5 + a];
                const float ps   = PS[psb + PP * 32 * a];
                const float aa   = DB[k] - dold;
                const float Dv   = sp2(aa + ps) - sp2(aa);
                D[wb + 16 * a] = Dv;
                av += (k != jv) ? sm[OFF_W + k] * Dv : 0.f;
            }
            acc[v] = av;
        }
        /* rowsum: 16 threads contribute per row */
        #pragma unroll
        for (int v = 0; v < 5; ++v) {
            const int jm = tid + NTH * v;
            const int jv = jm - (jm / S) * S;
            atomicAdd(&sm[OFF_RS + jv], acc[v]);
        }
        __syncthreads();   /* d + RS complete */

        /* ---- Δb all-reduce across the 6 ranks ---- */
        const int buf = it & 1;
        float myPart = 0.f;
        if (tid < S) {
            myPart = sm[OFF_RS + tid];
            const uint32_t dst = accAddr + 4u * (uint32_t)(buf * S + tid);
            #pragma unroll
            for (int r = 0; r < 6; ++r)
                if (r != rank) red_remote_add_f32(dst, (uint32_t)r, myPart);
        }
        cluster_sync_();   /* peer partials landed */
        if (tid < S) {
            const float tot = myPart + sm[OFF_ACC + buf * S + tid];
            sm[OFF_ACC + buf * S + tid] = 0.f;      /* re-arm for it+2 */
            sm[OFF_RS + tid] = 0.f;
            dbFinal = sm[OFF_SE + tid] + sm[OFF_MJ + tid] * tot;
            DB[tid] = dbFinal;
        }
        /* next iter's post-stage __syncthreads orders DB/RS/ACC for all */
    }

    /* ---- output: out[b, j, i, :] = softmax over channels (base-2) ---- */
    if (rank == 0 && tid < S) {
        const float Dv = dbFinal;
        const float e  = ex2f_(-fabsf(Dv));
        const float pb = 1.f / (1.f + e);
        const float ps = e * pb;
        const float p1 = (Dv >= 0.f) ? pb : ps;
        const float p0 = (Dv >= 0.f) ? ps : pb;
        float* o = out + ((size_t)((b * S + tid) * S + i)) * 2;
        o[0] = p0;
        o[1] = p1;
    }
}

extern "C" void kernel_launch(void* const* d_in, const int* in_sizes, int n_in,
                              void* d_out, int out_size) {
    (void)in_sizes; (void)n_in; (void)out_size;
    cudaFuncSetAttribute(lbp_kernel,
                         cudaFuncAttributeMaxDynamicSharedMemorySize, SMEM_BYTES);
    const float* s_edge = (const float*)d_in[0];
    const float* s_sib  = (const float*)d_in[1];
    const float* s_cop  = (const float*)d_in[2];
    const float* s_grd  = (const float*)d_in[3];
    const void*  mask   = d_in[4];
    float* outp = (float*)d_out;

    lbp_kernel<<<2 * S * 6, NTH, SMEM_BYTES>>>(
        s_edge, s_sib, s_cop, s_grd, mask, outp);
}

// round 7
// speedup vs baseline: 1.8988x; 1.0454x over previous
#include <cuda_runtime.h>
#include <cstdint>

// LBP semantic dependency, difference-space. 6-CTA cluster per (i,b) problem:
// rank r -> (type t = r>>1, parity c = r&1). Each CTA holds d[t] restricted to
// cells (j,k) with (j+k)&1==c (transpose partner same class -> CTA-local),
// plus P = 2^(p*log2e) staged in smem ONCE (iteration-invariant).
// Per-cell update uses the 3-MUFU identity:
//   D = lg2(1 + e*P) - lg2(1 + e),  e = 2^clamp(db[k]-dold, +-30)

#define S    160
#define S2   25600
#define S3   4096000
#define HS   80
#define DP   81          /* d pitch (odd: conflict-free row writes) */
#define PP   80          /* ps pitch (transpose reads conflict-free) */
#define NTH  512
#define LOG2E 1.4426950408889634f

/* shared layout (floats) */
#define OFF_D    0                    /* d[160][81] = 12960 */
#define OFF_PS   12960                /* P[160][80] = 12800 */
#define OFF_DB   25760                /* deltab[160] */
#define OFF_SE   25920
#define OFF_W    26080
#define OFF_MJ   26240
#define OFF_RS   26400                /* local rowsum[160] */
#define OFF_ACC  26560                /* peer partial sums [2][160] */
#define SMEM_FLOATS (OFF_ACC + 2*S)
#define SMEM_BYTES  (SMEM_FLOATS * 4)

extern __shared__ float sm[];

__device__ __forceinline__ uint32_t smem_u32(const void* p) {
    uint32_t a;
    asm("{ .reg .u64 t; cvta.to.shared.u64 t, %1; cvt.u32.u64 %0, t; }"
        : "=r"(a) : "l"(p));
    return a;
}
__device__ __forceinline__ void cluster_sync_() {
    asm volatile("barrier.cluster.arrive.aligned;" ::: "memory");
    asm volatile("barrier.cluster.wait.aligned;" ::: "memory");
}
__device__ __forceinline__ void red_remote_add_f32(uint32_t laddr, uint32_t rank, float v) {
    asm volatile(
        "{ .reg .b32 r; mapa.shared::cluster.u32 r, %0, %1; "
        "red.relaxed.cluster.shared::cluster.add.f32 [r], %2; }"
        :: "r"(laddr), "r"(rank), "f"(v) : "memory");
}
__device__ __forceinline__ float ex2f_(float x) {
    float y; asm("ex2.approx.ftz.f32 %0, %1;" : "=f"(y) : "f"(x)); return y;
}
__device__ __forceinline__ float lg2f_(float x) {
    float y; asm("lg2.approx.ftz.f32 %0, %1;" : "=f"(y) : "f"(x)); return y;
}
__device__ __forceinline__ bool mask_at(const void* m, bool byteMask, int idx) {
    if (byteMask) return ((const unsigned char*)m)[idx] != 0;
    return ((const uint32_t*)m)[idx] != 0u;
}

__global__ void __launch_bounds__(NTH, 2) __cluster_dims__(6, 1, 1)
lbp_kernel(const float* __restrict__ s_edge,
           const float* __restrict__ s_sib,
           const float* __restrict__ s_cop,
           const float* __restrict__ s_grd,
           const void* __restrict__ mask,
           float* __restrict__ out)
{
    const int tid  = threadIdx.x;
    const int bx   = blockIdx.x;
    const int rank = bx % 6;
    const int prob = bx / 6;
    const int i    = prob % S;
    const int b    = prob / S;
    const int t    = rank >> 1;      /* score type */
    const int c    = rank & 1;       /* pair-parity class */

    const bool byteMask = (*(const uint32_t*)mask == 0x01010101u);

    float* __restrict__ D  = sm + OFF_D;
    float* __restrict__ PS = sm + OFF_PS;
    float* __restrict__ DB = sm + OFF_DB;

    const float* __restrict__ P =
        (t == 0 ? s_sib : (t == 1 ? s_cop : s_grd)) + (size_t)b * S3 + i * S;

    /* ---- init: zero d, stage P = 2^(p*log2e) (once!), scalars ---- */
    #pragma unroll 4
    for (int u = 0; u < 26; ++u) {
        const int x = tid + NTH * u;
        if (x < S * DP) D[x] = 0.f;
    }
    #pragma unroll 5
    for (int u = 0; u < 50; ++u) {
        const int e   = tid + NTH * u;          /* 25600 = 512*50 exactly */
        const int col = e % S;
        const int r   = e / S;
        const float val = ex2f_(P[(size_t)r * S2 + col] * LOG2E);
        if (((r + col) & 1) == c) PS[r * PP + (col >> 1)] = val;
    }
    if (tid < S) {
        const int k = tid;
        const bool mk = mask_at(mask, byteMask, b * S2 + k * S + i);
        sm[OFF_W  + k] = (mk && (k != i)) ? 1.f : 0.f;
        sm[OFF_MJ + k] = mk ? 1.f : 0.f;
        sm[OFF_SE + k] = s_edge[b * S2 + k * S + i] * LOG2E;
        DB[k] = 0.f;
        sm[OFF_RS + k] = 0.f;
        sm[OFF_ACC + k] = 0.f;
        sm[OFF_ACC + S + k] = 0.f;
    }
    __syncthreads();
    cluster_sync_();   /* all ranks' ACC zeroed before any remote red */

    const uint32_t accAddr = smem_u32(sm + OFF_ACC);
    float dbFinal = 0.f;

    for (int it = 0; it < 3; ++it) {
        /* ---- stage transpose partners d_old[k][j] into regs ----
           cell (jv, k), k = kB + 32*a; partner d[k][jv] at row k, col jv>>1 */
        float dreg[25];
        #pragma unroll
        for (int v = 0; v < 5; ++v) {
            const int jm  = tid + NTH * v;
            const int kkB = jm / S;
            const int jv  = jm - kkB * S;
            const int kB  = 2 * kkB + (c ^ (jv & 1));
            const int tb  = kB * DP + (jv >> 1);
            #pragma unroll
            for (int a = 0; a < 5; ++a)
                dreg[v * 5 + a] = D[tb + DP * 32 * a];
        }
        __syncthreads();   /* all reads of d before any writes */

        /* ---- compute new message differences (3 MUFU/cell) ---- */
        float acc[5];
        #pragma unroll
        for (int v = 0; v < 5; ++v) {
            const int jm  = tid + NTH * v;
            const int kkB = jm / S;
            const int jv  = jm - kkB * S;
            const int par = c ^ (jv & 1);
            const int kB  = 2 * kkB + par;
            const int psb = kB * PP + (jv >> 1);
            const int wb  = jv * DP + kkB;
            float av = 0.f;
            #pragma unroll
            for (int a = 0; a < 5; ++a) {
                const int k  = kB + 32 * a;
                const float aa = fminf(fmaxf(DB[k] - dreg[v * 5 + a], -30.f), 30.f);
                const float e  = ex2f_(aa);
                const float Pv = PS[psb + PP * 32 * a];
                const float Dv = lg2f_(fmaf(e, Pv, 1.f)) - lg2f_(e + 1.f);
                D[wb + 16 * a] = Dv;
                av += (k != jv) ? sm[OFF_W + k] * Dv : 0.f;
            }
            acc[v] = av;
        }
        /* rowsum: 16 threads contribute per row */
        #pragma unroll
        for (int v = 0; v < 5; ++v) {
            const int jm = tid + NTH * v;
            const int jv = jm - (jm / S) * S;
            atomicAdd(&sm[OFF_RS + jv], acc[v]);
        }
        __syncthreads();   /* d + RS complete */

        /* ---- Δb all-reduce across the 6 ranks ---- */
        const int buf = it & 1;
        float myPart = 0.f;
        if (tid < S) {
            myPart = sm[OFF_RS + tid];
            const uint32_t dst = accAddr + 4u * (uint32_t)(buf * S + tid);
            #pragma unroll
            for (int r = 0; r < 6; ++r)
                if (r != rank) red_remote_add_f32(dst, (uint32_t)r, myPart);
        }
        cluster_sync_();   /* peer partials landed */
        if (tid < S) {
            const float tot = myPart + sm[OFF_ACC + buf * S + tid];
            sm[OFF_ACC + buf * S + tid] = 0.f;      /* re-arm for it+2 */
            sm[OFF_RS + tid] = 0.f;
            dbFinal = sm[OFF_SE + tid] + sm[OFF_MJ + tid] * tot;
            DB[tid] = dbFinal;
        }
        /* next iter's post-stage __syncthreads orders DB/RS/ACC for all */
    }

    /* ---- output: out[b, j, i, :] = softmax over channels (base-2) ---- */
    if (rank == 0 && tid < S) {
        const float Dv = dbFinal;
        const float e  = ex2f_(-fabsf(Dv));
        const float pb = 1.f / (1.f + e);
        const float ps = e * pb;
        const float p1 = (Dv >= 0.f) ? pb : ps;
        const float p0 = (Dv >= 0.f) ? ps : pb;
        float* o = out + ((size_t)((b * S + tid) * S + i)) * 2;
        o[0] = p0;
        o[1] = p1;
    }
}

extern "C" void kernel_launch(void* const* d_in, const int* in_sizes, int n_in,
                              void* d_out, int out_size) {
    (void)in_sizes; (void)n_in; (void)out_size;
    cudaFuncSetAttribute(lbp_kernel,
                         cudaFuncAttributeMaxDynamicSharedMemorySize, SMEM_BYTES);
    const float* s_edge = (const float*)d_in[0];
    const float* s_sib  = (const float*)d_in[1];
    const float* s_cop  = (const float*)d_in[2];
    const float* s_grd  = (const float*)d_in[3];
    const void*  mask   = d_in[4];
    float* outp = (float*)d_out;

    lbp_kernel<<<2 * S * 6, NTH, SMEM_BYTES>>>(
        s_edge, s_sib, s_cop, s_grd, mask, outp);
}